// round 1
// baseline (speedup 1.0000x reference)
#include <cuda_runtime.h>
#include <math.h>

#define D        32
#define SPLITS   8
#define TT       64
#define BLK      256
#define QT       2
#define QB       (BLK*QT)      // 512 queries per block
#define M_MAX    16384
#define N_MAX    8192
#define EPSV     1e-8f

// ---------------- device scratch (no allocations allowed) ----------------
__device__ float        g_c;                       // 1/(2*bw^2)
__device__ float        g_t2[N_MAX];               // train row squared norms
__device__ float        g_pnum[SPLITS][M_MAX];     // partial weighted sums
__device__ float        g_pden[SPLITS][M_MAX];     // partial weight sums
__device__ float        g_rx[M_MAX];
__device__ unsigned int g_rmin, g_rmax, g_smin, g_smax;  // ordered-uint encoded

// ---------------- helpers ----------------
__device__ __forceinline__ unsigned long long pack2(float lo, float hi) {
    unsigned long long r;
    asm("mov.b64 %0, {%1, %2};" : "=l"(r) : "f"(lo), "f"(hi));
    return r;
}
__device__ __forceinline__ unsigned long long fma2(unsigned long long a,
                                                   unsigned long long b,
                                                   unsigned long long c) {
    unsigned long long d;
    asm("fma.rn.f32x2 %0, %1, %2, %3;" : "=l"(d) : "l"(a), "l"(b), "l"(c));
    return d;
}
__device__ __forceinline__ float2 unpack2(unsigned long long p) {
    float2 f;
    asm("mov.b64 {%0, %1}, %2;" : "=f"(f.x), "=f"(f.y) : "l"(p));
    return f;
}
// monotone float <-> uint map (works for negatives too)
__device__ __forceinline__ unsigned int fenc(float f) {
    unsigned int u = __float_as_uint(f);
    return (u & 0x80000000u) ? ~u : (u | 0x80000000u);
}
__device__ __forceinline__ float fdec(unsigned int u) {
    u = (u & 0x80000000u) ? (u & 0x7fffffffu) : ~u;
    return __uint_as_float(u);
}
__device__ __forceinline__ float warp_min(float v) {
    #pragma unroll
    for (int o = 16; o; o >>= 1) v = fminf(v, __shfl_xor_sync(0xffffffffu, v, o));
    return v;
}
__device__ __forceinline__ float warp_max(float v) {
    #pragma unroll
    for (int o = 16; o; o >>= 1) v = fmaxf(v, __shfl_xor_sync(0xffffffffu, v, o));
    return v;
}

// ---------------- kernel 1: Scott bandwidth + scalar init ----------------
// 1024 threads = 32 warps; warp w reduces dimension w over n rows (double acc).
__global__ void k_bw(const float* __restrict__ tx, int n) {
    __shared__ double s_std[32];
    int w = threadIdx.x >> 5, l = threadIdx.x & 31;
    double s = 0.0, s2 = 0.0;
    for (int r = l; r < n; r += 32) {
        double v = (double)tx[(size_t)r * D + w];
        s += v; s2 += v * v;
    }
    #pragma unroll
    for (int o = 16; o; o >>= 1) {
        s  += __shfl_down_sync(0xffffffffu, s,  o);
        s2 += __shfl_down_sync(0xffffffffu, s2, o);
    }
    if (l == 0) {
        double mean = s / (double)n;
        double var  = (s2 - (double)n * mean * mean) / (double)(n - 1);
        s_std[w] = sqrt(var > 0.0 ? var : 0.0);
    }
    __syncthreads();
    if (threadIdx.x == 0) {
        double ms = 0.0;
        #pragma unroll
        for (int i = 0; i < D; i++) ms += s_std[i];
        ms /= (double)D;
        double bw = ms * exp(-log((double)n) / (double)(D + 4));
        g_c = (float)(1.0 / (2.0 * bw * bw));
        g_rmin = 0xFFFFFFFFu; g_rmax = 0u;
        g_smin = 0xFFFFFFFFu; g_smax = 0u;
    }
}

// ---------------- kernel 2: train row norms ----------------
__global__ void k_t2(const float* __restrict__ tx, int n) {
    int j = blockIdx.x * blockDim.x + threadIdx.x;
    if (j >= n) return;
    const float4* r = (const float4*)(tx + (size_t)j * D);
    float s = 0.f;
    #pragma unroll
    for (int k = 0; k < D / 4; k++) {
        float4 v = r[k];
        s = fmaf(v.x, v.x, s); s = fmaf(v.y, v.y, s);
        s = fmaf(v.z, v.z, s); s = fmaf(v.w, v.w, s);
    }
    g_t2[j] = s;
}

// ---------------- kernel 3: pairwise KDE mainloop ----------------
// grid = (m/QB, SPLITS); each thread owns 2 queries (registers), train tiles in SMEM.
__global__ void __launch_bounds__(BLK, 2)
k_main(const float* __restrict__ x, const float* __restrict__ tx,
       const float* __restrict__ tr, int m, int n) {
    __shared__ float sh_t[TT * D];
    __shared__ float sh_r[TT];
    __shared__ float sh_t2[TT];

    const float c = g_c;
    const int tid = threadIdx.x;
    const int q0  = blockIdx.x * QB + tid * 2;

    // load 2 query rows into packed u64 registers + squared norms
    unsigned long long qr0[D / 2], qr1[D / 2];
    float q2_0 = 0.f, q2_1 = 0.f;
    {
        const float4* p0 = (const float4*)(x + (size_t)q0 * D);
        const float4* p1 = (const float4*)(x + (size_t)(q0 + 1) * D);
        #pragma unroll
        for (int k = 0; k < D / 4; k++) {
            float4 a = p0[k], b = p1[k];
            qr0[2 * k]     = pack2(a.x, a.y);
            qr0[2 * k + 1] = pack2(a.z, a.w);
            qr1[2 * k]     = pack2(b.x, b.y);
            qr1[2 * k + 1] = pack2(b.z, b.w);
            q2_0 = fmaf(a.x, a.x, q2_0); q2_0 = fmaf(a.y, a.y, q2_0);
            q2_0 = fmaf(a.z, a.z, q2_0); q2_0 = fmaf(a.w, a.w, q2_0);
            q2_1 = fmaf(b.x, b.x, q2_1); q2_1 = fmaf(b.y, b.y, q2_1);
            q2_1 = fmaf(b.z, b.z, q2_1); q2_1 = fmaf(b.w, b.w, q2_1);
        }
    }

    float num0 = 0.f, den0 = 0.f, num1 = 0.f, den1 = 0.f;
    const int nsplit = n / SPLITS;
    const int j_lo = blockIdx.y * nsplit;
    const int j_hi = j_lo + nsplit;

    for (int jt = j_lo; jt < j_hi; jt += TT) {
        // cooperative coalesced tile load
        {
            const float4* src = (const float4*)(tx + (size_t)jt * D);
            float4* dst = (float4*)sh_t;
            #pragma unroll
            for (int i = tid; i < TT * D / 4; i += BLK) dst[i] = src[i];
            if (tid < TT) { sh_r[tid] = tr[jt + tid]; sh_t2[tid] = g_t2[jt + tid]; }
        }
        __syncthreads();

        #pragma unroll 2
        for (int t = 0; t < TT; t++) {
            const ulonglong2* tv = ((const ulonglong2*)sh_t) + t * (D / 4);
            unsigned long long a0x = 0ull, a0y = 0ull, a1x = 0ull, a1y = 0ull;
            #pragma unroll
            for (int k = 0; k < D / 4; k++) {
                ulonglong2 w = tv[k];
                a0x = fma2(qr0[2 * k],     w.x, a0x);
                a0y = fma2(qr0[2 * k + 1], w.y, a0y);
                a1x = fma2(qr1[2 * k],     w.x, a1x);
                a1y = fma2(qr1[2 * k + 1], w.y, a1y);
            }
            float2 u0 = unpack2(a0x), v0 = unpack2(a0y);
            float2 u1 = unpack2(a1x), v1 = unpack2(a1y);
            float dot0 = (u0.x + u0.y) + (v0.x + v0.y);
            float dot1 = (u1.x + u1.y) + (v1.x + v1.y);
            float t2v = sh_t2[t], rv = sh_r[t];
            float d20 = fmaxf(fmaf(-2.f, dot0, q2_0 + t2v), 0.f);
            float d21 = fmaxf(fmaf(-2.f, dot1, q2_1 + t2v), 0.f);
            float w0 = __expf(-d20 * c);
            float w1 = __expf(-d21 * c);
            num0 = fmaf(w0, rv, num0); den0 += w0;
            num1 = fmaf(w1, rv, num1); den1 += w1;
        }
        __syncthreads();
    }

    if (q0 + 1 < m) {
        g_pnum[blockIdx.y][q0]     = num0;
        g_pden[blockIdx.y][q0]     = den0;
        g_pnum[blockIdx.y][q0 + 1] = num1;
        g_pden[blockIdx.y][q0 + 1] = den1;
    }
}

// ---------------- kernel 4: reduce splits -> rx, block min/max for rx & sigma ----------------
__global__ void k_reduce(const float* __restrict__ sig, int m) {
    __shared__ float s_rmin[8], s_rmax[8], s_smin[8], s_smax[8];
    int q = blockIdx.x * blockDim.x + threadIdx.x;
    float rx = 3.4e38f, rxmx = -3.4e38f, sg = 3.4e38f, sgmx = -3.4e38f;
    if (q < m) {
        float num = 0.f, den = 0.f;
        #pragma unroll
        for (int s = 0; s < SPLITS; s++) { num += g_pnum[s][q]; den += g_pden[s][q]; }
        float r = num / (den + EPSV);
        g_rx[q] = r;
        rx = r; rxmx = r;
        float sv = sig[q];
        sg = sv; sgmx = sv;
    }
    float wmin_r = warp_min(rx),  wmax_r = warp_max(rxmx);
    float wmin_s = warp_min(sg),  wmax_s = warp_max(sgmx);
    int w = threadIdx.x >> 5, l = threadIdx.x & 31;
    if (l == 0) { s_rmin[w] = wmin_r; s_rmax[w] = wmax_r; s_smin[w] = wmin_s; s_smax[w] = wmax_s; }
    __syncthreads();
    if (threadIdx.x == 0) {
        float bmin_r = s_rmin[0], bmax_r = s_rmax[0], bmin_s = s_smin[0], bmax_s = s_smax[0];
        #pragma unroll
        for (int i = 1; i < BLK / 32; i++) {
            bmin_r = fminf(bmin_r, s_rmin[i]); bmax_r = fmaxf(bmax_r, s_rmax[i]);
            bmin_s = fminf(bmin_s, s_smin[i]); bmax_s = fmaxf(bmax_s, s_smax[i]);
        }
        atomicMin(&g_rmin, fenc(bmin_r)); atomicMax(&g_rmax, fenc(bmax_r));
        atomicMin(&g_smin, fenc(bmin_s)); atomicMax(&g_smax, fenc(bmax_s));
    }
}

// ---------------- kernel 5: final normalize + combine ----------------
__global__ void k_final(const float* __restrict__ sig, float* __restrict__ out, int m) {
    int q = blockIdx.x * blockDim.x + threadIdx.x;
    if (q >= m) return;
    float rmin = fdec(g_rmin), rmax = fdec(g_rmax);
    float smin = fdec(g_smin), smax = fdec(g_smax);
    float t1 = 0.5f * (g_rx[q] - rmin) / (rmax - rmin + EPSV);
    float t2 = 0.5f * (sig[q]  - smin) / (smax - smin + EPSV);
    out[q] = t1 + t2;
}

// ---------------- launch ----------------
extern "C" void kernel_launch(void* const* d_in, const int* in_sizes, int n_in,
                              void* d_out, int out_size) {
    const float* x   = (const float*)d_in[0];   // [m, 32]
    const float* tx  = (const float*)d_in[1];   // [n, 32]
    const float* tr  = (const float*)d_in[2];   // [n]
    const float* sig = (const float*)d_in[3];   // [m]
    int m = in_sizes[0] / D;   // 16384
    int n = in_sizes[1] / D;   // 8192

    k_bw<<<1, 1024>>>(tx, n);
    k_t2<<<(n + 255) / 256, 256>>>(tx, n);
    dim3 grid(m / QB, SPLITS);
    k_main<<<grid, BLK>>>(x, tx, tr, m, n);
    k_reduce<<<(m + BLK - 1) / BLK, BLK>>>(sig, m);
    k_final<<<(m + BLK - 1) / BLK, BLK>>>(sig, (float*)d_out, m);
}

// round 2
// speedup vs baseline: 1.0273x; 1.0273x over previous
#include <cuda_runtime.h>
#include <math.h>

#define D        32
#define SPLITS   9
#define TT       64
#define BLK      128
#define QT       2
#define QB       (BLK*QT)      // 256 queries per block
#define M_MAX    16384
#define N_MAX    8192
#define EPSV     1e-8f

// ---------------- device scratch ----------------
__device__ float        g_cl;                      // c * log2(e),  c = 1/(2 bw^2)
__device__ float2       g_te[N_MAX];               // (-cl*t2, 1.0)
__device__ float2       g_rr[N_MAX];               // (r, 1.0)
__device__ float        g_pnum[SPLITS][M_MAX];
__device__ float        g_pden[SPLITS][M_MAX];
__device__ float        g_rx[M_MAX];
__device__ unsigned int g_rmin, g_rmax, g_smin, g_smax;

// ---------------- helpers ----------------
__device__ __forceinline__ unsigned long long pack2(float lo, float hi) {
    unsigned long long r;
    asm("mov.b64 %0, {%1, %2};" : "=l"(r) : "f"(lo), "f"(hi));
    return r;
}
__device__ __forceinline__ unsigned long long dup2(float v) {
    unsigned long long r;
    asm("mov.b64 %0, {%1, %1};" : "=l"(r) : "f"(v));
    return r;
}
__device__ __forceinline__ unsigned long long fma2(unsigned long long a,
                                                   unsigned long long b,
                                                   unsigned long long c) {
    unsigned long long d;
    asm("fma.rn.f32x2 %0, %1, %2, %3;" : "=l"(d) : "l"(a), "l"(b), "l"(c));
    return d;
}
__device__ __forceinline__ unsigned long long add2(unsigned long long a,
                                                   unsigned long long b) {
    unsigned long long d;
    asm("add.rn.f32x2 %0, %1, %2;" : "=l"(d) : "l"(a), "l"(b));
    return d;
}
__device__ __forceinline__ float2 unpack2(unsigned long long p) {
    float2 f;
    asm("mov.b64 {%0, %1}, %2;" : "=f"(f.x), "=f"(f.y) : "l"(p));
    return f;
}
__device__ __forceinline__ float ex2f(float a) {
    float r;
    asm("ex2.approx.f32 %0, %1;" : "=f"(r) : "f"(a));
    return r;
}
__device__ __forceinline__ unsigned int fenc(float f) {
    unsigned int u = __float_as_uint(f);
    return (u & 0x80000000u) ? ~u : (u | 0x80000000u);
}
__device__ __forceinline__ float fdec(unsigned int u) {
    u = (u & 0x80000000u) ? (u & 0x7fffffffu) : ~u;
    return __uint_as_float(u);
}
__device__ __forceinline__ float warp_min(float v) {
    #pragma unroll
    for (int o = 16; o; o >>= 1) v = fminf(v, __shfl_xor_sync(0xffffffffu, v, o));
    return v;
}
__device__ __forceinline__ float warp_max(float v) {
    #pragma unroll
    for (int o = 16; o; o >>= 1) v = fmaxf(v, __shfl_xor_sync(0xffffffffu, v, o));
    return v;
}

// ---------------- kernel 1: Scott bandwidth + scalar init ----------------
__global__ void k_bw(const float* __restrict__ tx, int n) {
    __shared__ double s_std[32];
    int w = threadIdx.x >> 5, l = threadIdx.x & 31;
    double s = 0.0, s2 = 0.0;
    for (int r = l; r < n; r += 32) {
        double v = (double)tx[(size_t)r * D + w];
        s += v; s2 += v * v;
    }
    #pragma unroll
    for (int o = 16; o; o >>= 1) {
        s  += __shfl_down_sync(0xffffffffu, s,  o);
        s2 += __shfl_down_sync(0xffffffffu, s2, o);
    }
    if (l == 0) {
        double mean = s / (double)n;
        double var  = (s2 - (double)n * mean * mean) / (double)(n - 1);
        s_std[w] = sqrt(var > 0.0 ? var : 0.0);
    }
    __syncthreads();
    if (threadIdx.x == 0) {
        double ms = 0.0;
        #pragma unroll
        for (int i = 0; i < D; i++) ms += s_std[i];
        ms /= (double)D;
        double bw = ms * exp(-log((double)n) / (double)(D + 4));
        double c  = 1.0 / (2.0 * bw * bw);
        g_cl = (float)(c * 1.4426950408889634);
        g_rmin = 0xFFFFFFFFu; g_rmax = 0u;
        g_smin = 0xFFFFFFFFu; g_smax = 0u;
    }
}

// ---------------- kernel 2: per-train-point extension vectors ----------------
__global__ void k_t2(const float* __restrict__ tx, const float* __restrict__ tr, int n) {
    int j = blockIdx.x * blockDim.x + threadIdx.x;
    if (j >= n) return;
    const float4* r = (const float4*)(tx + (size_t)j * D);
    float s = 0.f;
    #pragma unroll
    for (int k = 0; k < D / 4; k++) {
        float4 v = r[k];
        s = fmaf(v.x, v.x, s); s = fmaf(v.y, v.y, s);
        s = fmaf(v.z, v.z, s); s = fmaf(v.w, v.w, s);
    }
    float cl = g_cl;
    g_te[j] = make_float2(-cl * s, 1.0f);
    g_rr[j] = make_float2(tr[j], 1.0f);
}

// ---------------- kernel 3: pairwise KDE mainloop ----------------
__global__ void __launch_bounds__(BLK, 4)
k_main(const float* __restrict__ x, const float* __restrict__ tx, int m, int n) {
    __shared__ float  sh_t[TT * D];
    __shared__ float2 sh_te[TT];
    __shared__ float2 sh_rr[TT];

    const float cl = g_cl;
    const float K2 = cl + cl;                     // 2*c*log2e
    const int tid = threadIdx.x;
    const int q0  = blockIdx.x * QB + tid * 2;

    // load 2 query rows: pre-scaled by K2, plus extension pair (1, -cl*q2)
    unsigned long long qr0[D / 2 + 1], qr1[D / 2 + 1];
    {
        const float4* p0 = (const float4*)(x + (size_t)q0 * D);
        const float4* p1 = (const float4*)(x + (size_t)(q0 + 1) * D);
        float q2_0 = 0.f, q2_1 = 0.f;
        #pragma unroll
        for (int k = 0; k < D / 4; k++) {
            float4 a = p0[k], b = p1[k];
            q2_0 = fmaf(a.x, a.x, q2_0); q2_0 = fmaf(a.y, a.y, q2_0);
            q2_0 = fmaf(a.z, a.z, q2_0); q2_0 = fmaf(a.w, a.w, q2_0);
            q2_1 = fmaf(b.x, b.x, q2_1); q2_1 = fmaf(b.y, b.y, q2_1);
            q2_1 = fmaf(b.z, b.z, q2_1); q2_1 = fmaf(b.w, b.w, q2_1);
            qr0[2 * k]     = pack2(a.x * K2, a.y * K2);
            qr0[2 * k + 1] = pack2(a.z * K2, a.w * K2);
            qr1[2 * k]     = pack2(b.x * K2, b.y * K2);
            qr1[2 * k + 1] = pack2(b.z * K2, b.w * K2);
        }
        qr0[D / 2] = pack2(1.0f, -cl * q2_0);
        qr1[D / 2] = pack2(1.0f, -cl * q2_1);
    }

    unsigned long long nd0 = 0ull, nd1 = 0ull;   // packed (num, den)

    const int NT = n / TT;
    const int tb_lo = (blockIdx.y * NT) / SPLITS;
    const int tb_hi = ((blockIdx.y + 1) * NT) / SPLITS;

    for (int tb = tb_lo; tb < tb_hi; tb++) {
        const int jt = tb * TT;
        {
            const float4* src = (const float4*)(tx + (size_t)jt * D);
            float4* dst = (float4*)sh_t;
            for (int i = tid; i < TT * D / 4; i += BLK) dst[i] = src[i];
            if (tid < TT) { sh_te[tid] = g_te[jt + tid]; sh_rr[tid] = g_rr[jt + tid]; }
        }
        __syncthreads();

        #pragma unroll 2
        for (int t = 0; t < TT; t++) {
            const ulonglong2* tv = ((const ulonglong2*)sh_t) + t * (D / 4);
            unsigned long long a0x = 0ull, a0y = 0ull, a1x = 0ull, a1y = 0ull;
            #pragma unroll
            for (int k = 0; k < D / 4; k++) {
                ulonglong2 w = tv[k];
                a0x = fma2(qr0[2 * k],     w.x, a0x);
                a0y = fma2(qr0[2 * k + 1], w.y, a0y);
                a1x = fma2(qr1[2 * k],     w.x, a1x);
                a1y = fma2(qr1[2 * k + 1], w.y, a1y);
            }
            unsigned long long te = *(const unsigned long long*)&sh_te[t];
            a0x = fma2(qr0[D / 2], te, a0x);     // adds (-cl*t2, -cl*q2)
            a1x = fma2(qr1[D / 2], te, a1x);
            unsigned long long s0 = add2(a0x, a0y);
            unsigned long long s1 = add2(a1x, a1y);
            float2 f0 = unpack2(s0), f1 = unpack2(s1);
            float arg0 = fminf(f0.x + f0.y, 0.f);
            float arg1 = fminf(f1.x + f1.y, 0.f);
            float w0 = ex2f(arg0);
            float w1 = ex2f(arg1);
            unsigned long long rr = *(const unsigned long long*)&sh_rr[t];
            nd0 = fma2(dup2(w0), rr, nd0);       // (num += w*r, den += w)
            nd1 = fma2(dup2(w1), rr, nd1);
        }
        __syncthreads();
    }

    float2 r0 = unpack2(nd0), r1 = unpack2(nd1);
    g_pnum[blockIdx.y][q0]     = r0.x;
    g_pden[blockIdx.y][q0]     = r0.y;
    g_pnum[blockIdx.y][q0 + 1] = r1.x;
    g_pden[blockIdx.y][q0 + 1] = r1.y;
}

// ---------------- kernel 4: reduce splits -> rx, global min/max ----------------
__global__ void k_reduce(const float* __restrict__ sig, int m) {
    __shared__ float s_rmin[8], s_rmax[8], s_smin[8], s_smax[8];
    int q = blockIdx.x * blockDim.x + threadIdx.x;
    float rx = 3.4e38f, rxmx = -3.4e38f, sg = 3.4e38f, sgmx = -3.4e38f;
    if (q < m) {
        float num = 0.f, den = 0.f;
        #pragma unroll
        for (int s = 0; s < SPLITS; s++) { num += g_pnum[s][q]; den += g_pden[s][q]; }
        float r = num / (den + EPSV);
        g_rx[q] = r;
        rx = r; rxmx = r;
        float sv = sig[q];
        sg = sv; sgmx = sv;
    }
    float wmin_r = warp_min(rx),  wmax_r = warp_max(rxmx);
    float wmin_s = warp_min(sg),  wmax_s = warp_max(sgmx);
    int w = threadIdx.x >> 5, l = threadIdx.x & 31;
    int nw = blockDim.x >> 5;
    if (l == 0) { s_rmin[w] = wmin_r; s_rmax[w] = wmax_r; s_smin[w] = wmin_s; s_smax[w] = wmax_s; }
    __syncthreads();
    if (threadIdx.x == 0) {
        float bmin_r = s_rmin[0], bmax_r = s_rmax[0], bmin_s = s_smin[0], bmax_s = s_smax[0];
        for (int i = 1; i < nw; i++) {
            bmin_r = fminf(bmin_r, s_rmin[i]); bmax_r = fmaxf(bmax_r, s_rmax[i]);
            bmin_s = fminf(bmin_s, s_smin[i]); bmax_s = fmaxf(bmax_s, s_smax[i]);
        }
        atomicMin(&g_rmin, fenc(bmin_r)); atomicMax(&g_rmax, fenc(bmax_r));
        atomicMin(&g_smin, fenc(bmin_s)); atomicMax(&g_smax, fenc(bmax_s));
    }
}

// ---------------- kernel 5: final normalize + combine ----------------
__global__ void k_final(const float* __restrict__ sig, float* __restrict__ out, int m) {
    int q = blockIdx.x * blockDim.x + threadIdx.x;
    if (q >= m) return;
    float rmin = fdec(g_rmin), rmax = fdec(g_rmax);
    float smin = fdec(g_smin), smax = fdec(g_smax);
    float t1 = 0.5f * (g_rx[q] - rmin) / (rmax - rmin + EPSV);
    float t2 = 0.5f * (sig[q]  - smin) / (smax - smin + EPSV);
    out[q] = t1 + t2;
}

// ---------------- launch ----------------
extern "C" void kernel_launch(void* const* d_in, const int* in_sizes, int n_in,
                              void* d_out, int out_size) {
    const float* x   = (const float*)d_in[0];   // [m, 32]
    const float* tx  = (const float*)d_in[1];   // [n, 32]
    const float* tr  = (const float*)d_in[2];   // [n]
    const float* sig = (const float*)d_in[3];   // [m]
    int m = in_sizes[0] / D;   // 16384
    int n = in_sizes[1] / D;   // 8192

    k_bw<<<1, 1024>>>(tx, n);
    k_t2<<<(n + 255) / 256, 256>>>(tx, tr, n);
    dim3 grid(m / QB, SPLITS);
    k_main<<<grid, BLK>>>(x, tx, m, n);
    k_reduce<<<(m + 255) / 256, 256>>>(sig, m);
    k_final<<<(m + 255) / 256, 256>>>(sig, (float*)d_out, m);
}

// round 3
// speedup vs baseline: 1.6151x; 1.5721x over previous
#include <cuda_runtime.h>
#include <math.h>

#define D        32
#define SPLITS   9
#define TT       64
#define BLK      256
#define M_MAX    16384
#define N_MAX    8192
#define EPSV     1e-8f
#define BWB      64            // blocks in bandwidth phase-1

// ---------------- device scratch ----------------
__device__ float        g_cl;                       // c * log2(e)
__device__ float4       g_terr[N_MAX];              // (-cl*t2, 1, r, 1)
__device__ double       g_bws [BWB * D];            // per-block partial sums
__device__ double       g_bws2[BWB * D];            // per-block partial sumsq
__device__ float        g_pnum[SPLITS][M_MAX];
__device__ float        g_pden[SPLITS][M_MAX];
__device__ float        g_rx[M_MAX];
__device__ unsigned int g_rmin, g_rmax, g_smin, g_smax;

// ---------------- helpers ----------------
__device__ __forceinline__ unsigned long long pack2(float lo, float hi) {
    unsigned long long r;
    asm("mov.b64 %0, {%1, %2};" : "=l"(r) : "f"(lo), "f"(hi));
    return r;
}
__device__ __forceinline__ unsigned long long dup2(float v) {
    unsigned long long r;
    asm("mov.b64 %0, {%1, %1};" : "=l"(r) : "f"(v));
    return r;
}
__device__ __forceinline__ unsigned long long fma2(unsigned long long a,
                                                   unsigned long long b,
                                                   unsigned long long c) {
    unsigned long long d;
    asm("fma.rn.f32x2 %0, %1, %2, %3;" : "=l"(d) : "l"(a), "l"(b), "l"(c));
    return d;
}
__device__ __forceinline__ unsigned long long add2(unsigned long long a,
                                                   unsigned long long b) {
    unsigned long long d;
    asm("add.rn.f32x2 %0, %1, %2;" : "=l"(d) : "l"(a), "l"(b));
    return d;
}
__device__ __forceinline__ float2 unpack2(unsigned long long p) {
    float2 f;
    asm("mov.b64 {%0, %1}, %2;" : "=f"(f.x), "=f"(f.y) : "l"(p));
    return f;
}
__device__ __forceinline__ float ex2f(float a) {
    float r;
    asm("ex2.approx.f32 %0, %1;" : "=f"(r) : "f"(a));
    return r;
}
__device__ __forceinline__ void cp16(unsigned int dst_smem, const void* src) {
    asm volatile("cp.async.ca.shared.global [%0], [%1], 16;"
                 :: "r"(dst_smem), "l"(src));
}
__device__ __forceinline__ unsigned int fenc(float f) {
    unsigned int u = __float_as_uint(f);
    return (u & 0x80000000u) ? ~u : (u | 0x80000000u);
}
__device__ __forceinline__ float fdec(unsigned int u) {
    u = (u & 0x80000000u) ? (u & 0x7fffffffu) : ~u;
    return __uint_as_float(u);
}
__device__ __forceinline__ float warp_min(float v) {
    #pragma unroll
    for (int o = 16; o; o >>= 1) v = fminf(v, __shfl_xor_sync(0xffffffffu, v, o));
    return v;
}
__device__ __forceinline__ float warp_max(float v) {
    #pragma unroll
    for (int o = 16; o; o >>= 1) v = fmaxf(v, __shfl_xor_sync(0xffffffffu, v, o));
    return v;
}

// ---------------- bandwidth phase 1: coalesced per-block partials ----------------
// 64 blocks x 256 thr; block b handles rows [b*128, b*128+128). Thread covers
// float4-group g = tid&7 (dims 4g..4g+3), 4 row-chunks of 32 rows each.
__global__ void k_bw1(const float* __restrict__ tx) {
    __shared__ double sds [8][8][4];
    __shared__ double sds2[8][8][4];
    const int tid = threadIdx.x;
    const int b   = blockIdx.x;
    const float4* tx4 = (const float4*)tx;

    double s[4] = {0, 0, 0, 0}, s2[4] = {0, 0, 0, 0};
    #pragma unroll
    for (int it = 0; it < 4; it++) {
        // 256 threads cover 32 rows x 8 float4
        float4 v = tx4[(size_t)(b * 128 + it * 32) * 8 + tid];
        double vx = v.x, vy = v.y, vz = v.z, vw = v.w;
        s[0] += vx; s2[0] += vx * vx;
        s[1] += vy; s2[1] += vy * vy;
        s[2] += vz; s2[2] += vz * vz;
        s[3] += vw; s2[3] += vw * vw;
    }
    // combine lanes with identical g = lane&7 (xor 8, xor 16)
    #pragma unroll
    for (int o = 8; o <= 16; o <<= 1) {
        #pragma unroll
        for (int k = 0; k < 4; k++) {
            s [k] += __shfl_xor_sync(0xffffffffu, s [k], o);
            s2[k] += __shfl_xor_sync(0xffffffffu, s2[k], o);
        }
    }
    int w = tid >> 5, l = tid & 31;
    if (l < 8) {
        #pragma unroll
        for (int k = 0; k < 4; k++) { sds[w][l][k] = s[k]; sds2[w][l][k] = s2[k]; }
    }
    __syncthreads();
    if (tid < 8) {   // thread g reduces across 8 warps, writes dims 4g..4g+3
        #pragma unroll
        for (int k = 0; k < 4; k++) {
            double a = 0, a2 = 0;
            #pragma unroll
            for (int ww = 0; ww < 8; ww++) { a += sds[ww][tid][k]; a2 += sds2[ww][tid][k]; }
            g_bws [b * D + tid * 4 + k] = a;
            g_bws2[b * D + tid * 4 + k] = a2;
        }
    }
}

// ---------------- bandwidth phase 2: final std/bandwidth + init ----------------
__global__ void k_bw2(int n) {
    int d = threadIdx.x;           // 32 threads, one per dim
    double s = 0, s2 = 0;
    for (int b = 0; b < BWB; b++) { s += g_bws[b * D + d]; s2 += g_bws2[b * D + d]; }
    double mean = s / (double)n;
    double var  = (s2 - (double)n * mean * mean) / (double)(n - 1);
    double sd   = sqrt(var > 0.0 ? var : 0.0);
    #pragma unroll
    for (int o = 16; o; o >>= 1) sd += __shfl_xor_sync(0xffffffffu, sd, o);
    if (d == 0) {
        double ms = sd / (double)D;
        double bw = ms * exp(-log((double)n) / (double)(D + 4));
        double c  = 1.0 / (2.0 * bw * bw);
        g_cl = (float)(c * 1.4426950408889634);
        g_rmin = 0xFFFFFFFFu; g_rmax = 0u;
        g_smin = 0xFFFFFFFFu; g_smax = 0u;
    }
}

// ---------------- train extension vectors ----------------
__global__ void k_t2(const float* __restrict__ tx, const float* __restrict__ tr, int n) {
    int j = blockIdx.x * blockDim.x + threadIdx.x;
    if (j >= n) return;
    const float4* r = (const float4*)(tx + (size_t)j * D);
    float s = 0.f;
    #pragma unroll
    for (int k = 0; k < D / 4; k++) {
        float4 v = r[k];
        s = fmaf(v.x, v.x, s); s = fmaf(v.y, v.y, s);
        s = fmaf(v.z, v.z, s); s = fmaf(v.w, v.w, s);
    }
    g_terr[j] = make_float4(-g_cl * s, 1.0f, tr[j], 1.0f);
}

// ---------------- pairwise KDE mainloop ----------------
// 1 query/thread, 256 thr, occ 4 (32 warps/SM). Double-buffered cp.async tiles.
__global__ void __launch_bounds__(BLK, 4)
k_main(const float* __restrict__ x, const float* __restrict__ tx, int m, int n) {
    __shared__ float4 sh_c[2][TT * 8];   // train coords, 8 float4 per row
    __shared__ float4 sh_e[2][TT];       // (-cl*t2, 1, r, 1)

    const float cl = g_cl;
    const float K2 = cl + cl;
    const int tid = threadIdx.x;
    const int q   = blockIdx.x * BLK + tid;

    // query row: pre-scaled by 2*cl, extension pair (1, -cl*q2)
    unsigned long long qr[D / 2 + 1];
    {
        const float4* p = (const float4*)(x + (size_t)q * D);
        float q2 = 0.f;
        #pragma unroll
        for (int k = 0; k < D / 4; k++) {
            float4 a = p[k];
            q2 = fmaf(a.x, a.x, q2); q2 = fmaf(a.y, a.y, q2);
            q2 = fmaf(a.z, a.z, q2); q2 = fmaf(a.w, a.w, q2);
            qr[2 * k]     = pack2(a.x * K2, a.y * K2);
            qr[2 * k + 1] = pack2(a.z * K2, a.w * K2);
        }
        qr[D / 2] = pack2(1.0f, -cl * q2);
    }

    unsigned long long nd = 0ull;   // packed (num, den)

    const int NT = n / TT;
    const int tb_lo = (blockIdx.y * NT) / SPLITS;
    const int tb_hi = ((blockIdx.y + 1) * NT) / SPLITS;

    unsigned int sc0 = (unsigned int)__cvta_generic_to_shared(&sh_c[0][0]);
    unsigned int sc1 = (unsigned int)__cvta_generic_to_shared(&sh_c[1][0]);
    unsigned int se0 = (unsigned int)__cvta_generic_to_shared(&sh_e[0][0]);
    unsigned int se1 = (unsigned int)__cvta_generic_to_shared(&sh_e[1][0]);

    auto issue = [&](int tb, int buf) {
        const float4* src = ((const float4*)tx) + (size_t)tb * TT * 8;
        unsigned int dc = buf ? sc1 : sc0;
        unsigned int de = buf ? se1 : se0;
        cp16(dc + tid * 16, src + tid);
        cp16(dc + (tid + 256) * 16, src + tid + 256);
        if (tid < TT) cp16(de + tid * 16, g_terr + (size_t)tb * TT + tid);
        asm volatile("cp.async.commit_group;");
    };

    issue(tb_lo, 0);
    int buf = 0;
    for (int tb = tb_lo; tb < tb_hi; tb++) {
        if (tb + 1 < tb_hi) {
            issue(tb + 1, buf ^ 1);
            asm volatile("cp.async.wait_group 1;");
        } else {
            asm volatile("cp.async.wait_group 0;");
        }
        __syncthreads();

        const ulonglong2* cbase = (const ulonglong2*)(buf ? &sh_c[1][0] : &sh_c[0][0]);
        const ulonglong2* ebase = (const ulonglong2*)(buf ? &sh_e[1][0] : &sh_e[0][0]);

        #pragma unroll 4
        for (int t = 0; t < TT; t++) {
            const ulonglong2* tv = cbase + t * 8;
            unsigned long long ax = 0ull, ay = 0ull;
            #pragma unroll
            for (int k = 0; k < 8; k++) {
                ulonglong2 w = tv[k];
                ax = fma2(qr[2 * k],     w.x, ax);
                ay = fma2(qr[2 * k + 1], w.y, ay);
            }
            ulonglong2 e = ebase[t];
            ax = fma2(qr[D / 2], e.x, ax);       // += (-cl*t2, -cl*q2)
            unsigned long long sacc = add2(ax, ay);
            float2 f = unpack2(sacc);
            float arg = fminf(f.x + f.y, 0.f);
            float w = ex2f(arg);
            nd = fma2(dup2(w), e.y, nd);         // (num += w*r, den += w)
        }
        __syncthreads();
        buf ^= 1;
    }

    float2 r = unpack2(nd);
    g_pnum[blockIdx.y][q] = r.x;
    g_pden[blockIdx.y][q] = r.y;
}

// ---------------- reduce splits -> rx, global min/max ----------------
__global__ void k_reduce(const float* __restrict__ sig, int m) {
    __shared__ float s_rmin[8], s_rmax[8], s_smin[8], s_smax[8];
    int q = blockIdx.x * blockDim.x + threadIdx.x;
    float rx = 3.4e38f, rxmx = -3.4e38f, sg = 3.4e38f, sgmx = -3.4e38f;
    if (q < m) {
        float num = 0.f, den = 0.f;
        #pragma unroll
        for (int s = 0; s < SPLITS; s++) { num += g_pnum[s][q]; den += g_pden[s][q]; }
        float r = num / (den + EPSV);
        g_rx[q] = r;
        rx = r; rxmx = r;
        float sv = sig[q];
        sg = sv; sgmx = sv;
    }
    float wmin_r = warp_min(rx),  wmax_r = warp_max(rxmx);
    float wmin_s = warp_min(sg),  wmax_s = warp_max(sgmx);
    int w = threadIdx.x >> 5, l = threadIdx.x & 31;
    int nw = blockDim.x >> 5;
    if (l == 0) { s_rmin[w] = wmin_r; s_rmax[w] = wmax_r; s_smin[w] = wmin_s; s_smax[w] = wmax_s; }
    __syncthreads();
    if (threadIdx.x == 0) {
        float bmin_r = s_rmin[0], bmax_r = s_rmax[0], bmin_s = s_smin[0], bmax_s = s_smax[0];
        for (int i = 1; i < nw; i++) {
            bmin_r = fminf(bmin_r, s_rmin[i]); bmax_r = fmaxf(bmax_r, s_rmax[i]);
            bmin_s = fminf(bmin_s, s_smin[i]); bmax_s = fmaxf(bmax_s, s_smax[i]);
        }
        atomicMin(&g_rmin, fenc(bmin_r)); atomicMax(&g_rmax, fenc(bmax_r));
        atomicMin(&g_smin, fenc(bmin_s)); atomicMax(&g_smax, fenc(bmax_s));
    }
}

// ---------------- final normalize + combine ----------------
__global__ void k_final(const float* __restrict__ sig, float* __restrict__ out, int m) {
    int q = blockIdx.x * blockDim.x + threadIdx.x;
    if (q >= m) return;
    float rmin = fdec(g_rmin), rmax = fdec(g_rmax);
    float smin = fdec(g_smin), smax = fdec(g_smax);
    float t1 = 0.5f * (g_rx[q] - rmin) / (rmax - rmin + EPSV);
    float t2 = 0.5f * (sig[q]  - smin) / (smax - smin + EPSV);
    out[q] = t1 + t2;
}

// ---------------- launch ----------------
extern "C" void kernel_launch(void* const* d_in, const int* in_sizes, int n_in,
                              void* d_out, int out_size) {
    const float* x   = (const float*)d_in[0];   // [m, 32]
    const float* tx  = (const float*)d_in[1];   // [n, 32]
    const float* tr  = (const float*)d_in[2];   // [n]
    const float* sig = (const float*)d_in[3];   // [m]
    int m = in_sizes[0] / D;   // 16384
    int n = in_sizes[1] / D;   // 8192

    k_bw1<<<BWB, 256>>>(tx);
    k_bw2<<<1, 32>>>(n);
    k_t2<<<(n + 255) / 256, 256>>>(tx, tr, n);
    dim3 grid(m / BLK, SPLITS);
    k_main<<<grid, BLK>>>(x, tx, m, n);
    k_reduce<<<(m + 255) / 256, 256>>>(sig, m);
    k_final<<<(m + 255) / 256, 256>>>(sig, (float*)d_out, m);
}

// round 4
// speedup vs baseline: 1.8016x; 1.1155x over previous
#include <cuda_runtime.h>
#include <math.h>

#define D        32
#define SPLITS   9
#define TT       64
#define BLK      128
#define QT       2
#define QB       (BLK*QT)      // 256 queries per block
#define M_MAX    16384
#define N_MAX    8192
#define EPSV     1e-8f
#define BWB      64

// ---------------- device scratch ----------------
__device__ float        g_cl;                       // c * log2(e)
__device__ float4       g_terr[N_MAX];              // (-cl*t2, 1, r, 1)
__device__ double       g_bws [BWB * D];
__device__ double       g_bws2[BWB * D];
__device__ float        g_pnum[SPLITS][M_MAX];
__device__ float        g_pden[SPLITS][M_MAX];
__device__ float        g_rx[M_MAX];
__device__ unsigned int g_rmin, g_rmax, g_smin, g_smax;

// ---------------- helpers ----------------
__device__ __forceinline__ unsigned long long pack2(float lo, float hi) {
    unsigned long long r;
    asm("mov.b64 %0, {%1, %2};" : "=l"(r) : "f"(lo), "f"(hi));
    return r;
}
__device__ __forceinline__ unsigned long long dup2(float v) {
    unsigned long long r;
    asm("mov.b64 %0, {%1, %1};" : "=l"(r) : "f"(v));
    return r;
}
__device__ __forceinline__ unsigned long long fma2(unsigned long long a,
                                                   unsigned long long b,
                                                   unsigned long long c) {
    unsigned long long d;
    asm("fma.rn.f32x2 %0, %1, %2, %3;" : "=l"(d) : "l"(a), "l"(b), "l"(c));
    return d;
}
__device__ __forceinline__ unsigned long long add2(unsigned long long a,
                                                   unsigned long long b) {
    unsigned long long d;
    asm("add.rn.f32x2 %0, %1, %2;" : "=l"(d) : "l"(a), "l"(b));
    return d;
}
__device__ __forceinline__ float2 unpack2(unsigned long long p) {
    float2 f;
    asm("mov.b64 {%0, %1}, %2;" : "=f"(f.x), "=f"(f.y) : "l"(p));
    return f;
}
__device__ __forceinline__ float ex2f(float a) {
    float r;
    asm("ex2.approx.f32 %0, %1;" : "=f"(r) : "f"(a));
    return r;
}
__device__ __forceinline__ void cp16(unsigned int dst_smem, const void* src) {
    asm volatile("cp.async.ca.shared.global [%0], [%1], 16;"
                 :: "r"(dst_smem), "l"(src));
}
__device__ __forceinline__ unsigned int fenc(float f) {
    unsigned int u = __float_as_uint(f);
    return (u & 0x80000000u) ? ~u : (u | 0x80000000u);
}
__device__ __forceinline__ float fdec(unsigned int u) {
    u = (u & 0x80000000u) ? (u & 0x7fffffffu) : ~u;
    return __uint_as_float(u);
}
__device__ __forceinline__ float warp_min(float v) {
    #pragma unroll
    for (int o = 16; o; o >>= 1) v = fminf(v, __shfl_xor_sync(0xffffffffu, v, o));
    return v;
}
__device__ __forceinline__ float warp_max(float v) {
    #pragma unroll
    for (int o = 16; o; o >>= 1) v = fmaxf(v, __shfl_xor_sync(0xffffffffu, v, o));
    return v;
}

// ---------------- bandwidth phase 1 ----------------
__global__ void k_bw1(const float* __restrict__ tx) {
    __shared__ double sds [8][8][4];
    __shared__ double sds2[8][8][4];
    const int tid = threadIdx.x;
    const int b   = blockIdx.x;
    const float4* tx4 = (const float4*)tx;

    double s[4] = {0, 0, 0, 0}, s2[4] = {0, 0, 0, 0};
    #pragma unroll
    for (int it = 0; it < 4; it++) {
        float4 v = tx4[(size_t)(b * 128 + it * 32) * 8 + tid];
        double vx = v.x, vy = v.y, vz = v.z, vw = v.w;
        s[0] += vx; s2[0] += vx * vx;
        s[1] += vy; s2[1] += vy * vy;
        s[2] += vz; s2[2] += vz * vz;
        s[3] += vw; s2[3] += vw * vw;
    }
    #pragma unroll
    for (int o = 8; o <= 16; o <<= 1) {
        #pragma unroll
        for (int k = 0; k < 4; k++) {
            s [k] += __shfl_xor_sync(0xffffffffu, s [k], o);
            s2[k] += __shfl_xor_sync(0xffffffffu, s2[k], o);
        }
    }
    int w = tid >> 5, l = tid & 31;
    if (l < 8) {
        #pragma unroll
        for (int k = 0; k < 4; k++) { sds[w][l][k] = s[k]; sds2[w][l][k] = s2[k]; }
    }
    __syncthreads();
    if (tid < 8) {
        #pragma unroll
        for (int k = 0; k < 4; k++) {
            double a = 0, a2 = 0;
            #pragma unroll
            for (int ww = 0; ww < 8; ww++) { a += sds[ww][tid][k]; a2 += sds2[ww][tid][k]; }
            g_bws [b * D + tid * 4 + k] = a;
            g_bws2[b * D + tid * 4 + k] = a2;
        }
    }
}

// ---------------- bandwidth phase 2 ----------------
__global__ void k_bw2(int n) {
    int d = threadIdx.x;
    double s = 0, s2 = 0;
    for (int b = 0; b < BWB; b++) { s += g_bws[b * D + d]; s2 += g_bws2[b * D + d]; }
    double mean = s / (double)n;
    double var  = (s2 - (double)n * mean * mean) / (double)(n - 1);
    double sd   = sqrt(var > 0.0 ? var : 0.0);
    #pragma unroll
    for (int o = 16; o; o >>= 1) sd += __shfl_xor_sync(0xffffffffu, sd, o);
    if (d == 0) {
        double ms = sd / (double)D;
        double bw = ms * exp(-log((double)n) / (double)(D + 4));
        double c  = 1.0 / (2.0 * bw * bw);
        g_cl = (float)(c * 1.4426950408889634);
        g_rmin = 0xFFFFFFFFu; g_rmax = 0u;
        g_smin = 0xFFFFFFFFu; g_smax = 0u;
    }
}

// ---------------- train extension vectors ----------------
__global__ void k_t2(const float* __restrict__ tx, const float* __restrict__ tr, int n) {
    int j = blockIdx.x * blockDim.x + threadIdx.x;
    if (j >= n) return;
    const float4* r = (const float4*)(tx + (size_t)j * D);
    float s = 0.f;
    #pragma unroll
    for (int k = 0; k < D / 4; k++) {
        float4 v = r[k];
        s = fmaf(v.x, v.x, s); s = fmaf(v.y, v.y, s);
        s = fmaf(v.z, v.z, s); s = fmaf(v.w, v.w, s);
    }
    g_terr[j] = make_float4(-g_cl * s, 1.0f, tr[j], 1.0f);
}

// ---------------- pairwise KDE mainloop ----------------
// 2 queries/thread (q, q+BLK), 128 thr, occ 5. Double-buffered cp.async tiles.
__global__ void __launch_bounds__(BLK, 5)
k_main(const float* __restrict__ x, const float* __restrict__ tx, int m, int n) {
    __shared__ float4 sh_c[2][TT * 8];
    __shared__ float4 sh_e[2][TT];

    const float cl = g_cl;
    const float K2 = cl + cl;
    const int tid = threadIdx.x;
    const int q0  = blockIdx.x * QB + tid;
    const int q1  = q0 + BLK;

    unsigned long long qr0[D / 2 + 1], qr1[D / 2 + 1];
    {
        const float4* p0 = (const float4*)(x + (size_t)q0 * D);
        const float4* p1 = (const float4*)(x + (size_t)q1 * D);
        float q2_0 = 0.f, q2_1 = 0.f;
        #pragma unroll
        for (int k = 0; k < D / 4; k++) {
            float4 a = p0[k], b = p1[k];
            q2_0 = fmaf(a.x, a.x, q2_0); q2_0 = fmaf(a.y, a.y, q2_0);
            q2_0 = fmaf(a.z, a.z, q2_0); q2_0 = fmaf(a.w, a.w, q2_0);
            q2_1 = fmaf(b.x, b.x, q2_1); q2_1 = fmaf(b.y, b.y, q2_1);
            q2_1 = fmaf(b.z, b.z, q2_1); q2_1 = fmaf(b.w, b.w, q2_1);
            qr0[2 * k]     = pack2(a.x * K2, a.y * K2);
            qr0[2 * k + 1] = pack2(a.z * K2, a.w * K2);
            qr1[2 * k]     = pack2(b.x * K2, b.y * K2);
            qr1[2 * k + 1] = pack2(b.z * K2, b.w * K2);
        }
        qr0[D / 2] = pack2(1.0f, -cl * q2_0);
        qr1[D / 2] = pack2(1.0f, -cl * q2_1);
    }

    unsigned long long nd0 = 0ull, nd1 = 0ull;

    const int NT = n / TT;
    const int tb_lo = (blockIdx.y * NT) / SPLITS;
    const int tb_hi = ((blockIdx.y + 1) * NT) / SPLITS;

    unsigned int sc0 = (unsigned int)__cvta_generic_to_shared(&sh_c[0][0]);
    unsigned int sc1 = (unsigned int)__cvta_generic_to_shared(&sh_c[1][0]);
    unsigned int se0 = (unsigned int)__cvta_generic_to_shared(&sh_e[0][0]);
    unsigned int se1 = (unsigned int)__cvta_generic_to_shared(&sh_e[1][0]);

    auto issue = [&](int tb, int buf) {
        const float4* src = ((const float4*)tx) + (size_t)tb * TT * 8;
        unsigned int dc = buf ? sc1 : sc0;
        unsigned int de = buf ? se1 : se0;
        #pragma unroll
        for (int i = 0; i < 4; i++)
            cp16(dc + (tid + i * BLK) * 16, src + tid + i * BLK);
        if (tid < TT) cp16(de + tid * 16, g_terr + (size_t)tb * TT + tid);
        asm volatile("cp.async.commit_group;");
    };

    issue(tb_lo, 0);
    int buf = 0;
    for (int tb = tb_lo; tb < tb_hi; tb++) {
        if (tb + 1 < tb_hi) {
            issue(tb + 1, buf ^ 1);
            asm volatile("cp.async.wait_group 1;");
        } else {
            asm volatile("cp.async.wait_group 0;");
        }
        __syncthreads();

        const ulonglong2* cbase = (const ulonglong2*)(buf ? &sh_c[1][0] : &sh_c[0][0]);
        const ulonglong2* ebase = (const ulonglong2*)(buf ? &sh_e[1][0] : &sh_e[0][0]);

        #pragma unroll 2
        for (int t = 0; t < TT; t++) {
            const ulonglong2* tv = cbase + t * 8;
            unsigned long long a0x = 0ull, a0y = 0ull, a1x = 0ull, a1y = 0ull;
            #pragma unroll
            for (int k = 0; k < 8; k++) {
                ulonglong2 w = tv[k];
                a0x = fma2(qr0[2 * k],     w.x, a0x);
                a0y = fma2(qr0[2 * k + 1], w.y, a0y);
                a1x = fma2(qr1[2 * k],     w.x, a1x);
                a1y = fma2(qr1[2 * k + 1], w.y, a1y);
            }
            ulonglong2 e = ebase[t];
            a0x = fma2(qr0[D / 2], e.x, a0x);
            a1x = fma2(qr1[D / 2], e.x, a1x);
            unsigned long long s0 = add2(a0x, a0y);
            unsigned long long s1 = add2(a1x, a1y);
            float2 f0 = unpack2(s0), f1 = unpack2(s1);
            float arg0 = fminf(f0.x + f0.y, 0.f);
            float arg1 = fminf(f1.x + f1.y, 0.f);
            float w0 = ex2f(arg0);
            float w1 = ex2f(arg1);
            nd0 = fma2(dup2(w0), e.y, nd0);
            nd1 = fma2(dup2(w1), e.y, nd1);
        }
        __syncthreads();
        buf ^= 1;
    }

    float2 r0 = unpack2(nd0), r1 = unpack2(nd1);
    g_pnum[blockIdx.y][q0] = r0.x;
    g_pden[blockIdx.y][q0] = r0.y;
    g_pnum[blockIdx.y][q1] = r1.x;
    g_pden[blockIdx.y][q1] = r1.y;
}

// ---------------- reduce splits -> rx, global min/max ----------------
__global__ void k_reduce(const float* __restrict__ sig, int m) {
    __shared__ float s_rmin[8], s_rmax[8], s_smin[8], s_smax[8];
    int q = blockIdx.x * blockDim.x + threadIdx.x;
    float rx = 3.4e38f, rxmx = -3.4e38f, sg = 3.4e38f, sgmx = -3.4e38f;
    if (q < m) {
        float num = 0.f, den = 0.f;
        #pragma unroll
        for (int s = 0; s < SPLITS; s++) { num += g_pnum[s][q]; den += g_pden[s][q]; }
        float r = num / (den + EPSV);
        g_rx[q] = r;
        rx = r; rxmx = r;
        float sv = sig[q];
        sg = sv; sgmx = sv;
    }
    float wmin_r = warp_min(rx),  wmax_r = warp_max(rxmx);
    float wmin_s = warp_min(sg),  wmax_s = warp_max(sgmx);
    int w = threadIdx.x >> 5, l = threadIdx.x & 31;
    int nw = blockDim.x >> 5;
    if (l == 0) { s_rmin[w] = wmin_r; s_rmax[w] = wmax_r; s_smin[w] = wmin_s; s_smax[w] = wmax_s; }
    __syncthreads();
    if (threadIdx.x == 0) {
        float bmin_r = s_rmin[0], bmax_r = s_rmax[0], bmin_s = s_smin[0], bmax_s = s_smax[0];
        for (int i = 1; i < nw; i++) {
            bmin_r = fminf(bmin_r, s_rmin[i]); bmax_r = fmaxf(bmax_r, s_rmax[i]);
            bmin_s = fminf(bmin_s, s_smin[i]); bmax_s = fmaxf(bmax_s, s_smax[i]);
        }
        atomicMin(&g_rmin, fenc(bmin_r)); atomicMax(&g_rmax, fenc(bmax_r));
        atomicMin(&g_smin, fenc(bmin_s)); atomicMax(&g_smax, fenc(bmax_s));
    }
}

// ---------------- final normalize + combine ----------------
__global__ void k_final(const float* __restrict__ sig, float* __restrict__ out, int m) {
    int q = blockIdx.x * blockDim.x + threadIdx.x;
    if (q >= m) return;
    float rmin = fdec(g_rmin), rmax = fdec(g_rmax);
    float smin = fdec(g_smin), smax = fdec(g_smax);
    float t1 = 0.5f * (g_rx[q] - rmin) / (rmax - rmin + EPSV);
    float t2 = 0.5f * (sig[q]  - smin) / (smax - smin + EPSV);
    out[q] = t1 + t2;
}

// ---------------- launch ----------------
extern "C" void kernel_launch(void* const* d_in, const int* in_sizes, int n_in,
                              void* d_out, int out_size) {
    const float* x   = (const float*)d_in[0];   // [m, 32]
    const float* tx  = (const float*)d_in[1];   // [n, 32]
    const float* tr  = (const float*)d_in[2];   // [n]
    const float* sig = (const float*)d_in[3];   // [m]
    int m = in_sizes[0] / D;   // 16384
    int n = in_sizes[1] / D;   // 8192

    k_bw1<<<BWB, 256>>>(tx);
    k_bw2<<<1, 32>>>(n);
    k_t2<<<(n + 255) / 256, 256>>>(tx, tr, n);
    dim3 grid(m / QB, SPLITS);
    k_main<<<grid, BLK>>>(x, tx, m, n);
    k_reduce<<<(m + 255) / 256, 256>>>(sig, m);
    k_final<<<(m + 255) / 256, 256>>>(sig, (float*)d_out, m);
}